// round 1
// baseline (speedup 1.0000x reference)
#include <cuda_runtime.h>
#include <math.h>

// Problem constants (fixed by the reference setup_inputs)
#define Bv     32
#define Dv     64
#define Hv     32
#define Wv     32
#define Kv     1024
#define HWv    (Hv * Wv)            // 1024
#define NROWS  (Bv * Hv * Wv)       // 32768
#define EPSV       1e-12f
#define PERP_EPSV  1e-10f

#define TILE_K   128                // codebooks per shared tile (128*64*4 = 32 KB)
#define THREADS  256

// Scratch (no device allocation allowed in kernel_launch)
__device__ float        g_cnorm[Kv];
__device__ unsigned int g_counts[Kv];

// ---------------------------------------------------------------------------
// Kernel 1: codebook squared norms + zero the usage histogram
// ---------------------------------------------------------------------------
__global__ void nsvq_prep_kernel(const float* __restrict__ cb) {
    int k = blockIdx.x * blockDim.x + threadIdx.x;
    if (k < Kv) {
        const float4* row = reinterpret_cast<const float4*>(cb + k * Dv);
        float s = 0.f;
        #pragma unroll
        for (int i = 0; i < Dv / 4; i++) {
            float4 v = row[i];
            s += v.x * v.x + v.y * v.y + v.z * v.z + v.w * v.w;
        }
        g_cnorm[k]  = s;
        g_counts[k] = 0u;
    }
}

// ---------------------------------------------------------------------------
// Kernel 2: fused distance-argmin + NSVQ noise injection + histogram
// One thread per row. x row lives in 64 registers; codebooks stream through
// shared memory in 32KB tiles (broadcast LDS reads, conflict-free).
// ---------------------------------------------------------------------------
__global__ __launch_bounds__(THREADS) void nsvq_main_kernel(
    const float* __restrict__ inputs,   // (B, D, H, W) NCHW
    const float* __restrict__ cb,       // (K, D)
    const float* __restrict__ noise,    // (N, D)
    float*       __restrict__ out)      // (B, D, H, W) NCHW
{
    __shared__ float sC[TILE_K * Dv];
    __shared__ float sN[TILE_K];

    const int n  = blockIdx.x * THREADS + threadIdx.x;   // row id, grid covers exactly NROWS
    const int b  = n / HWv;
    const int hw = n % HWv;
    const float* xin = inputs + (size_t)b * Dv * HWv + hw;

    // Load x row: stride HWv between channels; coalesced across the warp.
    float x[Dv];
    #pragma unroll
    for (int d = 0; d < Dv; d++) x[d] = xin[(size_t)d * HWv];

    float best = 3.402823466e38f;
    int   bidx = 0;

    for (int t = 0; t < Kv; t += TILE_K) {
        __syncthreads();
        // Cooperative tile load (vectorized)
        const float4* src = reinterpret_cast<const float4*>(cb + (size_t)t * Dv);
        float4*       dst = reinterpret_cast<float4*>(sC);
        #pragma unroll
        for (int i = threadIdx.x; i < TILE_K * Dv / 4; i += THREADS) dst[i] = src[i];
        for (int i = threadIdx.x; i < TILE_K; i += THREADS) sN[i] = g_cnorm[t + i];
        __syncthreads();

        #pragma unroll 4
        for (int k = 0; k < TILE_K; k++) {
            const float* c = sC + k * Dv;
            float dot = 0.f;
            #pragma unroll
            for (int d = 0; d < Dv; d++) dot = fmaf(x[d], c[d], dot);
            float dist = sN[k] - 2.f * dot;    // ||x||^2 omitted (constant per row)
            if (dist < best) { best = dist; bidx = t + k; }
        }
    }

    // norm of (x - c_best)
    const float* cbest = cb + (size_t)bidx * Dv;
    float nb = 0.f;
    #pragma unroll
    for (int d = 0; d < Dv; d++) {
        float diff = x[d] - cbest[d];
        nb = fmaf(diff, diff, nb);
    }

    // norm of noise row (contiguous, vectorized)
    const float4* nr4 = reinterpret_cast<const float4*>(noise + (size_t)n * Dv);
    float nn = 0.f;
    float nz[Dv];
    #pragma unroll
    for (int i = 0; i < Dv / 4; i++) {
        float4 v = nr4[i];
        nz[4*i+0] = v.x; nz[4*i+1] = v.y; nz[4*i+2] = v.z; nz[4*i+3] = v.w;
        nn += v.x * v.x + v.y * v.y + v.z * v.z + v.w * v.w;
    }

    const float scale = sqrtf(nb) / sqrtf(nn) + EPSV;

    float* yo = out + (size_t)b * Dv * HWv + hw;
    #pragma unroll
    for (int d = 0; d < Dv; d++) yo[(size_t)d * HWv] = fmaf(scale, nz[d], x[d]);

    atomicAdd(&g_counts[bidx], 1u);
}

// ---------------------------------------------------------------------------
// Kernel 3: perplexity from the histogram
// ---------------------------------------------------------------------------
__global__ void nsvq_perp_kernel(float* __restrict__ out_scalar) {
    __shared__ float warp_sums[8];
    const int tid = threadIdx.x;

    float s = 0.f;
    for (int k = tid; k < Kv; k += 256) {
        float p = (float)g_counts[k] * (1.0f / (float)NROWS);
        s += p * logf(p + PERP_EPSV);
    }
    // warp reduce
    #pragma unroll
    for (int off = 16; off > 0; off >>= 1)
        s += __shfl_down_sync(0xffffffffu, s, off);
    if ((tid & 31) == 0) warp_sums[tid >> 5] = s;
    __syncthreads();
    if (tid < 8) {
        float v = warp_sums[tid];
        #pragma unroll
        for (int off = 4; off > 0; off >>= 1)
            v += __shfl_down_sync(0xffu, v, off);
        if (tid == 0) *out_scalar = expf(-v);
    }
}

// ---------------------------------------------------------------------------
extern "C" void kernel_launch(void* const* d_in, const int* in_sizes, int n_in,
                              void* d_out, int out_size) {
    const float* inputs = (const float*)d_in[0];   // (32, 64, 32, 32)
    const float* cb     = (const float*)d_in[1];   // (1024, 64)
    const float* noise  = (const float*)d_in[2];   // (32768, 64)
    float*       out    = (float*)d_out;           // quantized (2097152) + perplexity (1)

    nsvq_prep_kernel<<<(Kv + 255) / 256, 256>>>(cb);
    nsvq_main_kernel<<<NROWS / THREADS, THREADS>>>(inputs, cb, noise, out);
    nsvq_perp_kernel<<<1, 256>>>(out + (size_t)NROWS * Dv);
}

// round 2
// speedup vs baseline: 1.0726x; 1.0726x over previous
#include <cuda_runtime.h>
#include <math.h>

// Problem constants (fixed by the reference setup_inputs)
#define Bv     32
#define Dv     64
#define Hv     32
#define Wv     32
#define Kv     1024
#define HWv    (Hv * Wv)            // 1024
#define NROWS  (Bv * Hv * Wv)       // 32768
#define EPSV       1e-12f
#define PERP_EPSV  1e-10f

#define TILE_K   128                // codebooks per shared tile (128*64*4 = 32 KB)
#define THREADS  256

typedef unsigned long long ull;

// Scratch (no device allocation allowed in kernel_launch)
__device__ float        g_cnorm[Kv];
__device__ unsigned int g_counts[Kv];

// ---- packed f32x2 helpers (sm_103a FFMA2) ---------------------------------
__device__ __forceinline__ ull pack2(float lo, float hi) {
    ull r;
    asm("mov.b64 %0, {%1, %2};" : "=l"(r) : "f"(lo), "f"(hi));
    return r;
}
__device__ __forceinline__ void unpack2(ull v, float& lo, float& hi) {
    asm("mov.b64 {%0, %1}, %2;" : "=f"(lo), "=f"(hi) : "l"(v));
}
__device__ __forceinline__ ull fma2(ull a, ull b, ull c) {
    ull d;
    asm("fma.rn.f32x2 %0, %1, %2, %3;" : "=l"(d) : "l"(a), "l"(b), "l"(c));
    return d;
}

// ---------------------------------------------------------------------------
// Kernel 1: codebook squared norms + zero the usage histogram
// ---------------------------------------------------------------------------
__global__ void nsvq_prep_kernel(const float* __restrict__ cb) {
    int k = blockIdx.x * blockDim.x + threadIdx.x;
    if (k < Kv) {
        const float4* row = reinterpret_cast<const float4*>(cb + k * Dv);
        float s = 0.f;
        #pragma unroll
        for (int i = 0; i < Dv / 4; i++) {
            float4 v = row[i];
            s += v.x * v.x + v.y * v.y + v.z * v.z + v.w * v.w;
        }
        g_cnorm[k]  = s;
        g_counts[k] = 0u;
    }
}

// ---------------------------------------------------------------------------
// Kernel 2: fused distance-argmin + NSVQ noise injection + histogram.
// One thread per row. x row packed into 32x f32x2 registers; codebooks stream
// through 32KB shared tiles read as ulonglong2 (LDS.128 -> two packed operands).
// Inner dot = 32 FFMA2 (2 chains) instead of 64 FFMA: 2x fp32 throughput.
// ---------------------------------------------------------------------------
__global__ __launch_bounds__(THREADS) void nsvq_main_kernel(
    const float* __restrict__ inputs,   // (B, D, H, W) NCHW
    const float* __restrict__ cb,       // (K, D)
    const float* __restrict__ noise,    // (N, D)
    float*       __restrict__ out)      // (B, D, H, W) NCHW
{
    __shared__ __align__(16) float sC[TILE_K * Dv];
    __shared__ float sN[TILE_K];

    const int n  = blockIdx.x * THREADS + threadIdx.x;   // row id (grid covers NROWS)
    const int b  = n / HWv;
    const int hw = n % HWv;
    const float* xin = inputs + (size_t)b * Dv * HWv + hw;

    // Load x row (stride HWv between channels; coalesced across warp) and pack pairs.
    ull x2[Dv / 2];
    #pragma unroll
    for (int i = 0; i < Dv / 2; i++) {
        float lo = xin[(size_t)(2 * i)     * HWv];
        float hi = xin[(size_t)(2 * i + 1) * HWv];
        x2[i] = pack2(lo, hi);
    }

    float best = 3.402823466e38f;
    int   bidx = 0;

    for (int t = 0; t < Kv; t += TILE_K) {
        __syncthreads();
        // Cooperative tile load (vectorized)
        const float4* src = reinterpret_cast<const float4*>(cb + (size_t)t * Dv);
        float4*       dst = reinterpret_cast<float4*>(sC);
        #pragma unroll
        for (int i = threadIdx.x; i < TILE_K * Dv / 4; i += THREADS) dst[i] = src[i];
        for (int i = threadIdx.x; i < TILE_K; i += THREADS) sN[i] = g_cnorm[t + i];
        __syncthreads();

        #pragma unroll 2
        for (int k = 0; k < TILE_K; k++) {
            const ulonglong2* c4 = reinterpret_cast<const ulonglong2*>(sC + k * Dv);
            ull acc0 = 0ull, acc1 = 0ull;      // packed (0.f, 0.f)
            #pragma unroll
            for (int i = 0; i < Dv / 4; i++) { // 16 iters: LDS.128 -> 2 FFMA2
                ulonglong2 cv = c4[i];
                acc0 = fma2(x2[2 * i],     cv.x, acc0);
                acc1 = fma2(x2[2 * i + 1], cv.y, acc1);
            }
            float a0l, a0h, a1l, a1h;
            unpack2(acc0, a0l, a0h);
            unpack2(acc1, a1l, a1h);
            float dot  = (a0l + a0h) + (a1l + a1h);
            float dist = fmaf(-2.f, dot, sN[k]);   // ||x||^2 omitted (const per row)
            if (dist < best) { best = dist; bidx = t + k; }
        }
    }

    // norm of (x - c_best)
    const float* cbest = cb + (size_t)bidx * Dv;
    float nb = 0.f;
    #pragma unroll
    for (int i = 0; i < Dv / 2; i++) {
        float xl, xh;
        unpack2(x2[i], xl, xh);
        float d0 = xl - cbest[2 * i];
        float d1 = xh - cbest[2 * i + 1];
        nb = fmaf(d0, d0, nb);
        nb = fmaf(d1, d1, nb);
    }

    // norm of noise row (contiguous, vectorized)
    const float4* nr4 = reinterpret_cast<const float4*>(noise + (size_t)n * Dv);
    float nn = 0.f;
    float nz[Dv];
    #pragma unroll
    for (int i = 0; i < Dv / 4; i++) {
        float4 v = nr4[i];
        nz[4*i+0] = v.x; nz[4*i+1] = v.y; nz[4*i+2] = v.z; nz[4*i+3] = v.w;
        nn += v.x * v.x + v.y * v.y + v.z * v.z + v.w * v.w;
    }

    const float scale = sqrtf(nb) / sqrtf(nn) + EPSV;

    float* yo = out + (size_t)b * Dv * HWv + hw;
    #pragma unroll
    for (int i = 0; i < Dv / 2; i++) {
        float xl, xh;
        unpack2(x2[i], xl, xh);
        yo[(size_t)(2 * i)     * HWv] = fmaf(scale, nz[2 * i],     xl);
        yo[(size_t)(2 * i + 1) * HWv] = fmaf(scale, nz[2 * i + 1], xh);
    }

    atomicAdd(&g_counts[bidx], 1u);
}

// ---------------------------------------------------------------------------
// Kernel 3: perplexity from the histogram
// ---------------------------------------------------------------------------
__global__ void nsvq_perp_kernel(float* __restrict__ out_scalar) {
    __shared__ float warp_sums[8];
    const int tid = threadIdx.x;

    float s = 0.f;
    for (int k = tid; k < Kv; k += 256) {
        float p = (float)g_counts[k] * (1.0f / (float)NROWS);
        s += p * logf(p + PERP_EPSV);
    }
    #pragma unroll
    for (int off = 16; off > 0; off >>= 1)
        s += __shfl_down_sync(0xffffffffu, s, off);
    if ((tid & 31) == 0) warp_sums[tid >> 5] = s;
    __syncthreads();
    if (tid < 8) {
        float v = warp_sums[tid];
        #pragma unroll
        for (int off = 4; off > 0; off >>= 1)
            v += __shfl_down_sync(0xffu, v, off);
        if (tid == 0) *out_scalar = expf(-v);
    }
}

// ---------------------------------------------------------------------------
extern "C" void kernel_launch(void* const* d_in, const int* in_sizes, int n_in,
                              void* d_out, int out_size) {
    const float* inputs = (const float*)d_in[0];   // (32, 64, 32, 32)
    const float* cb     = (const float*)d_in[1];   // (1024, 64)
    const float* noise  = (const float*)d_in[2];   // (32768, 64)
    float*       out    = (float*)d_out;           // quantized (2097152) + perplexity (1)

    nsvq_prep_kernel<<<(Kv + 255) / 256, 256>>>(cb);
    nsvq_main_kernel<<<NROWS / THREADS, THREADS>>>(inputs, cb, noise, out);
    nsvq_perp_kernel<<<1, 256>>>(out + (size_t)NROWS * Dv);
}

// round 5
// speedup vs baseline: 2.9091x; 2.7123x over previous
#include <cuda_runtime.h>
#include <cuda_bf16.h>
#include <cstdint>
#include <math.h>

// ---------------- problem constants ----------------
#define Dv      64
#define HWv     1024
#define NROWS   32768
#define Kv      1024
#define EPSV        1e-12f
#define PERP_EPSV   1e-10f

#define M_TILE   256                 // rows per CTA (one thread per row for epilogue)
#define THREADS  256                 // 8 warps
#define N_CHUNK  256                 // codebooks per SMEM chunk
#define NUM_CHK  (Kv / N_CHUNK)      // 4

// ---------------- SMEM layout (byte offsets into dynamic smem) ----------------
#define A_HI_OFF   0                            // 256 x 64 bf16 = 32KB
#define A_LO_OFF   32768
#define B_HI_OFF(b)  (65536  + (b) * 65536)     // 256 x 64 bf16 = 32KB
#define B_LO_OFF(b)  (98304  + (b) * 65536)
#define CN_OFF(b)    (196608 + (b) * 1024)      // 256 fp32 norms per buf
#define SIDX_OFF     198656                     // 256 x int
#define SMEM_DYN     199680

// ---------------- device scratch ----------------
__device__ __align__(16) float        g_cnorm[Kv];
__device__ unsigned int               g_counts[Kv];
// codebooks as bf16 hi/lo, PRE-SWIZZLED (16B-unit XOR by (row&7)<<4) so the
// main kernel cp.asyncs them linearly into SMEM.
__device__ __align__(16) unsigned char g_cb_hi[Kv * Dv * 2];
__device__ __align__(16) unsigned char g_cb_lo[Kv * Dv * 2];

// ---------------- helpers ----------------
__device__ __forceinline__ uint32_t smem_u32(const void* p) {
    uint32_t a;
    asm("{ .reg .u64 t; cvta.to.shared.u64 t, %1; cvt.u32.u64 %0, t; }"
        : "=r"(a) : "l"(p));
    return a;
}
// swizzled byte offset for (row, 16B-unit)
#define SWZ(row, unit) ((((uint32_t)(row) * 128u) + (uint32_t)(unit) * 16u) ^ ((((uint32_t)(row)) & 7u) << 4))

__device__ __forceinline__ void ldsm4(uint32_t addr, uint32_t& r0, uint32_t& r1,
                                      uint32_t& r2, uint32_t& r3) {
    asm volatile("ldmatrix.sync.aligned.m8n8.x4.shared.b16 {%0,%1,%2,%3}, [%4];"
                 : "=r"(r0), "=r"(r1), "=r"(r2), "=r"(r3) : "r"(addr));
}
__device__ __forceinline__ void mma_bf16(float* d, const uint32_t* a, const uint32_t* b) {
    asm volatile(
        "mma.sync.aligned.m16n8k16.row.col.f32.bf16.bf16.f32 "
        "{%0,%1,%2,%3}, {%4,%5,%6,%7}, {%8,%9}, {%0,%1,%2,%3};"
        : "+f"(d[0]), "+f"(d[1]), "+f"(d[2]), "+f"(d[3])
        : "r"(a[0]), "r"(a[1]), "r"(a[2]), "r"(a[3]), "r"(b[0]), "r"(b[1]));
}
__device__ __forceinline__ void cp16(uint32_t saddr, const void* g) {
    asm volatile("cp.async.cg.shared.global [%0], [%1], 16;" :: "r"(saddr), "l"(g));
}
#define CP_COMMIT() asm volatile("cp.async.commit_group;" ::: "memory")
#define CP_WAIT0()  asm volatile("cp.async.wait_group 0;"  ::: "memory")

// ---------------------------------------------------------------------------
// prep1: codebook squared norms (exact fp32) + zero histogram
// ---------------------------------------------------------------------------
__global__ void nsvq_prep_kernel(const float* __restrict__ cb) {
    int k = blockIdx.x * blockDim.x + threadIdx.x;
    if (k < Kv) {
        const float4* row = reinterpret_cast<const float4*>(cb + k * Dv);
        float s = 0.f;
        #pragma unroll
        for (int i = 0; i < Dv / 4; i++) {
            float4 v = row[i];
            s += v.x * v.x + v.y * v.y + v.z * v.z + v.w * v.w;
        }
        g_cnorm[k]  = s;
        g_counts[k] = 0u;
    }
}

// ---------------------------------------------------------------------------
// prep2: codebooks -> bf16 hi/lo split, stored pre-swizzled (16B-unit XOR).
// thread t handles (codebook k = t>>3, 16B-unit u = t&7) => 8 d-values.
// ---------------------------------------------------------------------------
__global__ void nsvq_prep2_kernel(const float* __restrict__ cb) {
    int t = blockIdx.x * blockDim.x + threadIdx.x;   // Kv*8 threads
    int k = t >> 3, u = t & 7;
    const float4* src = reinterpret_cast<const float4*>(cb + k * Dv + u * 8);
    float4 a = src[0], b = src[1];
    float v[8] = {a.x, a.y, a.z, a.w, b.x, b.y, b.z, b.w};
    unsigned short hs[8], ls[8];
    #pragma unroll
    for (int i = 0; i < 8; i++) {
        __nv_bfloat16 h = __float2bfloat16(v[i]);
        __nv_bfloat16 l = __float2bfloat16(v[i] - __bfloat162float(h));
        hs[i] = __bfloat16_as_ushort(h);
        ls[i] = __bfloat16_as_ushort(l);
    }
    uint32_t so = SWZ(k, u);
    uint4 ho, lo4;
    ho.x  = (uint32_t)hs[0] | ((uint32_t)hs[1] << 16);
    ho.y  = (uint32_t)hs[2] | ((uint32_t)hs[3] << 16);
    ho.z  = (uint32_t)hs[4] | ((uint32_t)hs[5] << 16);
    ho.w  = (uint32_t)hs[6] | ((uint32_t)hs[7] << 16);
    lo4.x = (uint32_t)ls[0] | ((uint32_t)ls[1] << 16);
    lo4.y = (uint32_t)ls[2] | ((uint32_t)ls[3] << 16);
    lo4.z = (uint32_t)ls[4] | ((uint32_t)ls[5] << 16);
    lo4.w = (uint32_t)ls[6] | ((uint32_t)ls[7] << 16);
    *reinterpret_cast<uint4*>(g_cb_hi + so) = ho;
    *reinterpret_cast<uint4*>(g_cb_lo + so) = lo4;
}

// ---------------------------------------------------------------------------
// main: bf16 HMMA distance GEMM (3-pass hi/lo) + fused argmin + NSVQ epilogue
// ---------------------------------------------------------------------------
__global__ __launch_bounds__(THREADS, 1)
void nsvq_hmma_kernel(const float* __restrict__ inputs,
                      const float* __restrict__ cbf,
                      const float* __restrict__ noise,
                      float*       __restrict__ out)
{
    extern __shared__ char sp[];
    const uint32_t sbase = smem_u32(sp);

    const int tid  = threadIdx.x;                    // row within tile
    const int wid  = tid >> 5;
    const int lane = tid & 31;
    const int n    = blockIdx.x * M_TILE + tid;      // global row
    const int bb   = n >> 10;
    const int hw   = n & 1023;

    // ---- load x row (regs) and write bf16 hi/lo into SMEM A (swizzled) ----
    const float* xin = inputs + (size_t)bb * (Dv * HWv) + hw;
    float x[Dv];
    #pragma unroll
    for (int d = 0; d < Dv; d++) x[d] = xin[(size_t)d * HWv];
    #pragma unroll
    for (int i = 0; i < Dv / 2; i++) {
        uint32_t off = SWZ(tid, i >> 2) + (uint32_t)(i & 3) * 4u;
        __nv_bfloat16 h0 = __float2bfloat16(x[2 * i]);
        __nv_bfloat16 h1 = __float2bfloat16(x[2 * i + 1]);
        __nv_bfloat16 l0 = __float2bfloat16(x[2 * i]     - __bfloat162float(h0));
        __nv_bfloat16 l1 = __float2bfloat16(x[2 * i + 1] - __bfloat162float(h1));
        *reinterpret_cast<uint32_t*>(sp + A_HI_OFF + off) =
            (uint32_t)__bfloat16_as_ushort(h0) | ((uint32_t)__bfloat16_as_ushort(h1) << 16);
        *reinterpret_cast<uint32_t*>(sp + A_LO_OFF + off) =
            (uint32_t)__bfloat16_as_ushort(l0) | ((uint32_t)__bfloat16_as_ushort(l1) << 16);
    }

    // ---- async-copy helper: chunk -> buffer ----
    auto issue_chunk = [&](int chunk, int buf) {
        const char* gh = (const char*)g_cb_hi + (size_t)chunk * 32768;
        const char* gl = (const char*)g_cb_lo + (size_t)chunk * 32768;
        const uint32_t dh = sbase + B_HI_OFF(buf);
        const uint32_t dl = sbase + B_LO_OFF(buf);
        #pragma unroll
        for (int i = 0; i < 8; i++) {
            uint32_t o = ((uint32_t)tid + (uint32_t)i * 256u) * 16u;
            cp16(dh + o, gh + o);
            cp16(dl + o, gl + o);
        }
        if (tid < 64)   // 64 threads x 16B = 1024B = 256 fp32 norms (R4 bug: was 16)
            cp16(sbase + CN_OFF(buf) + (uint32_t)tid * 16u,
                 (const char*)g_cnorm + (size_t)chunk * 1024 + (size_t)tid * 16);
    };

    issue_chunk(0, 0);
    CP_COMMIT();
    __syncthreads();   // A tiles visible to all warps

    // ---- load A fragments once (held in regs across all chunks) ----
    uint32_t ah[2][4][4], al[2][4][4];
    {
        const int arow = wid * 32 + (lane & 7) + ((lane >> 3) & 1) * 8;
        const int aun  = (lane >> 4);
        #pragma unroll
        for (int mt = 0; mt < 2; mt++) {
            #pragma unroll
            for (int kc = 0; kc < 4; kc++) {
                uint32_t ad = sbase + (uint32_t)SWZ(arow + mt * 16, kc * 2 + aun);
                ldsm4(ad + A_HI_OFF, ah[mt][kc][0], ah[mt][kc][1], ah[mt][kc][2], ah[mt][kc][3]);
                ldsm4(ad + A_LO_OFF, al[mt][kc][0], al[mt][kc][1], al[mt][kc][2], al[mt][kc][3]);
            }
        }
    }

    float best[4] = {3.402823466e38f, 3.402823466e38f, 3.402823466e38f, 3.402823466e38f};
    int   bidx[4] = {0, 0, 0, 0};

    const int browq = (lane & 7) + ((lane >> 4) & 1) * 8;   // B ldmatrix row within n16
    const int bunq  = (lane >> 3) & 1;                       // B ldmatrix k-unit parity

    for (int c = 0; c < NUM_CHK; c++) {
        CP_WAIT0();
        __syncthreads();                      // buffer (c&1) ready everywhere
        if (c + 1 < NUM_CHK) { issue_chunk(c + 1, (c + 1) & 1); CP_COMMIT(); }

        const int buf = c & 1;
        const float* cn = reinterpret_cast<const float*>(sp + CN_OFF(buf));
        const uint32_t bhb = sbase + B_HI_OFF(buf);
        const uint32_t blb = sbase + B_LO_OFF(buf);

        for (int g = 0; g < 16; g++) {        // n-groups of 16 codebooks
            const int n0 = g * 16;
            float acc[2][2][4];
            #pragma unroll
            for (int mt = 0; mt < 2; mt++)
                #pragma unroll
                for (int nt = 0; nt < 2; nt++)
                    #pragma unroll
                    for (int j = 0; j < 4; j++) acc[mt][nt][j] = 0.f;

            #pragma unroll
            for (int kc = 0; kc < 4; kc++) {
                uint32_t bo = (uint32_t)SWZ(n0 + browq, kc * 2 + bunq);
                uint32_t bh[4], bl[4];
                ldsm4(bhb + bo, bh[0], bh[1], bh[2], bh[3]);
                ldsm4(blb + bo, bl[0], bl[1], bl[2], bl[3]);
                #pragma unroll
                for (int mt = 0; mt < 2; mt++) {
                    mma_bf16(acc[mt][0], ah[mt][kc], bh + 0);
                    mma_bf16(acc[mt][1], ah[mt][kc], bh + 2);
                    mma_bf16(acc[mt][0], ah[mt][kc], bl + 0);
                    mma_bf16(acc[mt][1], ah[mt][kc], bl + 2);
                    mma_bf16(acc[mt][0], al[mt][kc], bh + 0);
                    mma_bf16(acc[mt][1], al[mt][kc], bh + 2);
                }
            }

            // dist + running argmin for this thread's 4 rows
            const int cb0 = n0 + 2 * (lane & 3);
            float cnl[4];
            {
                float2 p0 = *reinterpret_cast<const float2*>(cn + cb0);
                float2 p1 = *reinterpret_cast<const float2*>(cn + cb0 + 8);
                cnl[0] = p0.x; cnl[1] = p0.y; cnl[2] = p1.x; cnl[3] = p1.y;
            }
            const int kbase = c * N_CHUNK + cb0;
            #pragma unroll
            for (int mt = 0; mt < 2; mt++)
                #pragma unroll
                for (int nt = 0; nt < 2; nt++)
                    #pragma unroll
                    for (int j = 0; j < 4; j++) {
                        float dist = fmaf(-2.f, acc[mt][nt][j], cnl[nt * 2 + (j & 1)]);
                        int   kk   = kbase + nt * 8 + (j & 1);
                        int   s    = mt * 2 + (j >> 1);
                        if (dist < best[s]) { best[s] = dist; bidx[s] = kk; }
                    }
        }
        __syncthreads();                      // done reading buf before next overwrite cycle
    }

    // ---- quad butterfly reduce (lanes sharing the same rows) ----
    #pragma unroll
    for (int s = 0; s < 4; s++) {
        #pragma unroll
        for (int d = 1; d <= 2; d <<= 1) {
            float od = __shfl_xor_sync(0xffffffffu, best[s], d);
            int   oi = __shfl_xor_sync(0xffffffffu, bidx[s], d);
            if (od < best[s] || (od == best[s] && oi < bidx[s])) { best[s] = od; bidx[s] = oi; }
        }
    }
    // lane writes row = wid*32 + lane/4 + (lane%4)*8, slot = lane%4
    {
        int* sidx = reinterpret_cast<int*>(sp + SIDX_OFF);
        sidx[wid * 32 + (lane >> 2) + (lane & 3) * 8] = bidx[lane & 3];
    }
    __syncthreads();

    const int myidx = reinterpret_cast<const int*>(sp + SIDX_OFF)[tid];

    // ---- exact fp32 NSVQ epilogue for this thread's row ----
    const float4* cbest4 = reinterpret_cast<const float4*>(cbf + (size_t)myidx * Dv);
    float nb = 0.f;
    #pragma unroll
    for (int i = 0; i < Dv / 4; i++) {
        float4 cv = cbest4[i];
        float d0 = x[4 * i]     - cv.x;
        float d1 = x[4 * i + 1] - cv.y;
        float d2 = x[4 * i + 2] - cv.z;
        float d3 = x[4 * i + 3] - cv.w;
        nb = fmaf(d0, d0, nb); nb = fmaf(d1, d1, nb);
        nb = fmaf(d2, d2, nb); nb = fmaf(d3, d3, nb);
    }

    const float4* nr4 = reinterpret_cast<const float4*>(noise + (size_t)n * Dv);
    float nn = 0.f;
    float nz[Dv];
    #pragma unroll
    for (int i = 0; i < Dv / 4; i++) {
        float4 v = nr4[i];
        nz[4*i+0] = v.x; nz[4*i+1] = v.y; nz[4*i+2] = v.z; nz[4*i+3] = v.w;
        nn += v.x * v.x + v.y * v.y + v.z * v.z + v.w * v.w;
    }

    const float scale = sqrtf(nb) / sqrtf(nn) + EPSV;

    float* yo = out + (size_t)bb * (Dv * HWv) + hw;
    #pragma unroll
    for (int d = 0; d < Dv; d++) yo[(size_t)d * HWv] = fmaf(scale, nz[d], x[d]);

    atomicAdd(&g_counts[myidx], 1u);
}

// ---------------------------------------------------------------------------
// perplexity
// ---------------------------------------------------------------------------
__global__ void nsvq_perp_kernel(float* __restrict__ out_scalar) {
    __shared__ float warp_sums[8];
    const int tid = threadIdx.x;
    float s = 0.f;
    for (int k = tid; k < Kv; k += 256) {
        float p = (float)g_counts[k] * (1.0f / (float)NROWS);
        s += p * logf(p + PERP_EPSV);
    }
    #pragma unroll
    for (int off = 16; off > 0; off >>= 1)
        s += __shfl_down_sync(0xffffffffu, s, off);
    if ((tid & 31) == 0) warp_sums[tid >> 5] = s;
    __syncthreads();
    if (tid < 8) {
        float v = warp_sums[tid];
        #pragma unroll
        for (int off = 4; off > 0; off >>= 1)
            v += __shfl_down_sync(0xffu, v, off);
        if (tid == 0) *out_scalar = expf(-v);
    }
}

// ---------------------------------------------------------------------------
extern "C" void kernel_launch(void* const* d_in, const int* in_sizes, int n_in,
                              void* d_out, int out_size) {
    const float* inputs = (const float*)d_in[0];   // (32, 64, 32, 32)
    const float* cb     = (const float*)d_in[1];   // (1024, 64)
    const float* noise  = (const float*)d_in[2];   // (32768, 64)
    float*       out    = (float*)d_out;

    cudaFuncSetAttribute(nsvq_hmma_kernel,
                         cudaFuncAttributeMaxDynamicSharedMemorySize, SMEM_DYN);

    nsvq_prep_kernel<<<(Kv + 255) / 256, 256>>>(cb);
    nsvq_prep2_kernel<<<(Kv * 8) / 256, 256>>>(cb);
    nsvq_hmma_kernel<<<NROWS / M_TILE, THREADS, SMEM_DYN>>>(inputs, cb, noise, out);
    nsvq_perp_kernel<<<1, 256>>>(out + (size_t)NROWS * Dv);
}

// round 6
// speedup vs baseline: 4.3871x; 1.5081x over previous
#include <cuda_runtime.h>
#include <cuda_bf16.h>
#include <cstdint>
#include <math.h>

// ---------------- problem constants ----------------
#define Dv      64
#define HWv     1024
#define NROWS   32768
#define Kv      1024
#define EPSV        1e-12f
#define PERP_EPSV   1e-10f

#define M_TILE   256                 // rows per CTA (one thread per row for epilogue)
#define THREADS  256                 // 8 warps
#define GRID     (NROWS / M_TILE)    // 128 CTAs -> single wave

// ---------------- SMEM layout (byte offsets into dynamic smem) ----------------
#define A_OFF    0                   // 256 x 64 bf16 (swizzled rows of 128B) = 32KB
#define B_OFF    32768               // 1024 x 64 bf16 = 128KB
#define CN_OFF   163840              // 1024 fp32 norms = 4KB
#define SIDX_OFF 167936              // 256 x int (also reused for perp reduce)
#define SMEM_DYN 168960

// ---------------- device scratch ----------------
__device__ __align__(16) float        g_cnorm[Kv];
__device__ unsigned int               g_counts[Kv];
__device__ unsigned int               g_ticket;
// codebook as bf16, PRE-SWIZZLED (16B-unit XOR by (row&7)<<4) so the main
// kernel cp.asyncs it linearly into SMEM.
__device__ __align__(16) unsigned char g_cb[Kv * Dv * 2];

// ---------------- helpers ----------------
__device__ __forceinline__ uint32_t smem_u32(const void* p) {
    uint32_t a;
    asm("{ .reg .u64 t; cvta.to.shared.u64 t, %1; cvt.u32.u64 %0, t; }"
        : "=r"(a) : "l"(p));
    return a;
}
// swizzled byte offset for (row, 16B-unit)
#define SWZ(row, unit) ((((uint32_t)(row) * 128u) + (uint32_t)(unit) * 16u) ^ ((((uint32_t)(row)) & 7u) << 4))

__device__ __forceinline__ void ldsm4(uint32_t addr, uint32_t& r0, uint32_t& r1,
                                      uint32_t& r2, uint32_t& r3) {
    asm volatile("ldmatrix.sync.aligned.m8n8.x4.shared.b16 {%0,%1,%2,%3}, [%4];"
                 : "=r"(r0), "=r"(r1), "=r"(r2), "=r"(r3) : "r"(addr));
}
__device__ __forceinline__ void mma_bf16(float* d, const uint32_t* a, const uint32_t* b) {
    asm volatile(
        "mma.sync.aligned.m16n8k16.row.col.f32.bf16.bf16.f32 "
        "{%0,%1,%2,%3}, {%4,%5,%6,%7}, {%8,%9}, {%0,%1,%2,%3};"
        : "+f"(d[0]), "+f"(d[1]), "+f"(d[2]), "+f"(d[3])
        : "r"(a[0]), "r"(a[1]), "r"(a[2]), "r"(a[3]), "r"(b[0]), "r"(b[1]));
}
__device__ __forceinline__ void cp16(uint32_t saddr, const void* g) {
    asm volatile("cp.async.cg.shared.global [%0], [%1], 16;" :: "r"(saddr), "l"(g));
}
#define CP_COMMIT() asm volatile("cp.async.commit_group;" ::: "memory")
#define CP_WAIT0()  asm volatile("cp.async.wait_group 0;"  ::: "memory")

// ---------------------------------------------------------------------------
// prep (merged): codebook bf16 convert (pre-swizzled) + exact fp32 norms +
// zero histogram + reset ticket. thread t -> (codebook k = t>>3, 16B-unit u = t&7).
// ---------------------------------------------------------------------------
__global__ void nsvq_prep_kernel(const float* __restrict__ cb) {
    const int t = blockIdx.x * blockDim.x + threadIdx.x;   // Kv*8 = 8192 threads
    const int k = t >> 3, u = t & 7;
    const float4* src = reinterpret_cast<const float4*>(cb + k * Dv + u * 8);
    float4 a = src[0], b = src[1];
    float v[8] = {a.x, a.y, a.z, a.w, b.x, b.y, b.z, b.w};

    float part = 0.f;
    unsigned short hs[8];
    #pragma unroll
    for (int i = 0; i < 8; i++) {
        part = fmaf(v[i], v[i], part);
        hs[i] = __bfloat16_as_ushort(__float2bfloat16(v[i]));
    }
    // reduce the 8 lanes sharing one codebook row (u = low 3 bits of lane)
    part += __shfl_xor_sync(0xffffffffu, part, 1);
    part += __shfl_xor_sync(0xffffffffu, part, 2);
    part += __shfl_xor_sync(0xffffffffu, part, 4);
    if (u == 0) g_cnorm[k] = part;

    uint4 ho;
    ho.x = (uint32_t)hs[0] | ((uint32_t)hs[1] << 16);
    ho.y = (uint32_t)hs[2] | ((uint32_t)hs[3] << 16);
    ho.z = (uint32_t)hs[4] | ((uint32_t)hs[5] << 16);
    ho.w = (uint32_t)hs[6] | ((uint32_t)hs[7] << 16);
    *reinterpret_cast<uint4*>(g_cb + SWZ(k, u)) = ho;

    if (t < Kv)  g_counts[t] = 0u;
    if (t == 0)  g_ticket = 0u;
}

// ---------------------------------------------------------------------------
// main: bf16 HMMA distance GEMM (full codebook resident in SMEM) + fused
// argmin + exact fp32 NSVQ epilogue + last-CTA perplexity.
// ---------------------------------------------------------------------------
__global__ __launch_bounds__(THREADS, 1)
void nsvq_hmma_kernel(const float* __restrict__ inputs,
                      const float* __restrict__ cbf,
                      const float* __restrict__ noise,
                      float*       __restrict__ out)
{
    extern __shared__ char sp[];
    const uint32_t sbase = smem_u32(sp);

    const int tid  = threadIdx.x;                    // row within tile
    const int wid  = tid >> 5;
    const int lane = tid & 31;
    const int n    = blockIdx.x * M_TILE + tid;      // global row
    const int bb   = n >> 10;
    const int hw   = n & 1023;

    // ---- kick off async copy of the whole codebook + norms ----
    {
        const char* gb = (const char*)g_cb;
        #pragma unroll
        for (int i = 0; i < 32; i++) {               // 8192 x 16B = 128KB
            uint32_t o = ((uint32_t)tid + (uint32_t)i * 256u) * 16u;
            cp16(sbase + B_OFF + o, gb + o);
        }
        cp16(sbase + CN_OFF + (uint32_t)tid * 16u,   // 256 x 16B = 1024 norms
             (const char*)g_cnorm + (size_t)tid * 16);
        CP_COMMIT();
    }

    // ---- load x row (regs) and write bf16 into SMEM A (swizzled) ----
    const float* xin = inputs + (size_t)bb * (Dv * HWv) + hw;
    float x[Dv];
    #pragma unroll
    for (int d = 0; d < Dv; d++) x[d] = xin[(size_t)d * HWv];
    #pragma unroll
    for (int i = 0; i < Dv / 2; i++) {
        uint32_t off = SWZ(tid, i >> 2) + (uint32_t)(i & 3) * 4u;
        unsigned short h0 = __bfloat16_as_ushort(__float2bfloat16(x[2 * i]));
        unsigned short h1 = __bfloat16_as_ushort(__float2bfloat16(x[2 * i + 1]));
        *reinterpret_cast<uint32_t*>(sp + A_OFF + off) = (uint32_t)h0 | ((uint32_t)h1 << 16);
    }

    CP_WAIT0();
    __syncthreads();   // A + B + cn visible to all warps

    // ---- load A fragments once (held in regs) ----
    uint32_t ah[2][4][4];
    {
        const int arow = wid * 32 + (lane & 7) + ((lane >> 3) & 1) * 8;
        const int aun  = (lane >> 4);
        #pragma unroll
        for (int mt = 0; mt < 2; mt++)
            #pragma unroll
            for (int kc = 0; kc < 4; kc++) {
                uint32_t ad = sbase + A_OFF + (uint32_t)SWZ(arow + mt * 16, kc * 2 + aun);
                ldsm4(ad, ah[mt][kc][0], ah[mt][kc][1], ah[mt][kc][2], ah[mt][kc][3]);
            }
    }

    float best[4] = {3.402823466e38f, 3.402823466e38f, 3.402823466e38f, 3.402823466e38f};
    int   bidx[4] = {0, 0, 0, 0};

    const int browq = (lane & 7) + ((lane >> 4) & 1) * 8;   // B ldmatrix row within n16
    const int bunq  = (lane >> 3) & 1;                       // B ldmatrix k-unit parity
    const float* cn = reinterpret_cast<const float*>(sp + CN_OFF);

    #pragma unroll 2
    for (int g = 0; g < Kv / 16; g++) {               // 64 n-groups of 16 codebooks
        const int n0 = g * 16;
        float acc[2][2][4];
        #pragma unroll
        for (int mt = 0; mt < 2; mt++)
            #pragma unroll
            for (int nt = 0; nt < 2; nt++)
                #pragma unroll
                for (int j = 0; j < 4; j++) acc[mt][nt][j] = 0.f;

        #pragma unroll
        for (int kc = 0; kc < 4; kc++) {
            uint32_t bo = sbase + B_OFF + (uint32_t)SWZ(n0 + browq, kc * 2 + bunq);
            uint32_t bh[4];
            ldsm4(bo, bh[0], bh[1], bh[2], bh[3]);
            #pragma unroll
            for (int mt = 0; mt < 2; mt++) {
                mma_bf16(acc[mt][0], ah[mt][kc], bh + 0);
                mma_bf16(acc[mt][1], ah[mt][kc], bh + 2);
            }
        }

        // dist + running argmin for this thread's 4 (row, slot) pairs
        const int cb0 = n0 + 2 * (lane & 3);
        float cnl[4];
        {
            float2 p0 = *reinterpret_cast<const float2*>(cn + cb0);
            float2 p1 = *reinterpret_cast<const float2*>(cn + cb0 + 8);
            cnl[0] = p0.x; cnl[1] = p0.y; cnl[2] = p1.x; cnl[3] = p1.y;
        }
        #pragma unroll
        for (int mt = 0; mt < 2; mt++)
            #pragma unroll
            for (int nt = 0; nt < 2; nt++)
                #pragma unroll
                for (int j = 0; j < 4; j++) {
                    float dist = fmaf(-2.f, acc[mt][nt][j], cnl[nt * 2 + (j & 1)]);
                    int   kk   = cb0 + nt * 8 + (j & 1);
                    int   s    = mt * 2 + (j >> 1);
                    if (dist < best[s]) { best[s] = dist; bidx[s] = kk; }
                }
    }

    // ---- quad butterfly reduce (lanes sharing the same rows) ----
    #pragma unroll
    for (int s = 0; s < 4; s++) {
        #pragma unroll
        for (int d = 1; d <= 2; d <<= 1) {
            float od = __shfl_xor_sync(0xffffffffu, best[s], d);
            int   oi = __shfl_xor_sync(0xffffffffu, bidx[s], d);
            if (od < best[s] || (od == best[s] && oi < bidx[s])) { best[s] = od; bidx[s] = oi; }
        }
    }
    // lane writes row = wid*32 + lane/4 + (lane%4)*8, slot = lane%4
    {
        int* sidx = reinterpret_cast<int*>(sp + SIDX_OFF);
        sidx[wid * 32 + (lane >> 2) + (lane & 3) * 8] = bidx[lane & 3];
    }
    __syncthreads();

    const int myidx = reinterpret_cast<const int*>(sp + SIDX_OFF)[tid];

    // ---- exact fp32 NSVQ epilogue for this thread's row ----
    const float4* cbest4 = reinterpret_cast<const float4*>(cbf + (size_t)myidx * Dv);
    float nb = 0.f;
    #pragma unroll
    for (int i = 0; i < Dv / 4; i++) {
        float4 cv = cbest4[i];
        float d0 = x[4 * i]     - cv.x;
        float d1 = x[4 * i + 1] - cv.y;
        float d2 = x[4 * i + 2] - cv.z;
        float d3 = x[4 * i + 3] - cv.w;
        nb = fmaf(d0, d0, nb); nb = fmaf(d1, d1, nb);
        nb = fmaf(d2, d2, nb); nb = fmaf(d3, d3, nb);
    }

    const float4* nr4 = reinterpret_cast<const float4*>(noise + (size_t)n * Dv);
    float nn = 0.f;
    float nz[Dv];
    #pragma unroll
    for (int i = 0; i < Dv / 4; i++) {
        float4 v = nr4[i];
        nz[4*i+0] = v.x; nz[4*i+1] = v.y; nz[4*i+2] = v.z; nz[4*i+3] = v.w;
        nn += v.x * v.x + v.y * v.y + v.z * v.z + v.w * v.w;
    }

    const float scale = sqrtf(nb) / sqrtf(nn) + EPSV;

    float* yo = out + (size_t)bb * (Dv * HWv) + hw;
    #pragma unroll
    for (int d = 0; d < Dv; d++) yo[(size_t)d * HWv] = fmaf(scale, nz[d], x[d]);

    atomicAdd(&g_counts[myidx], 1u);

    // ---- last CTA computes perplexity ----
    __threadfence();
    __syncthreads();
    __shared__ unsigned int s_last;
    if (tid == 0) s_last = (atomicAdd(&g_ticket, 1u) == (unsigned)(GRID - 1)) ? 1u : 0u;
    __syncthreads();
    if (s_last) {
        float s = 0.f;
        for (int k = tid; k < Kv; k += THREADS) {
            float p = (float)g_counts[k] * (1.0f / (float)NROWS);
            s += p * logf(p + PERP_EPSV);
        }
        #pragma unroll
        for (int off = 16; off > 0; off >>= 1)
            s += __shfl_down_sync(0xffffffffu, s, off);
        float* ws = reinterpret_cast<float*>(sp + SIDX_OFF);
        if (lane == 0) ws[wid] = s;
        __syncthreads();
        if (tid < 8) {
            float v = ws[tid];
            #pragma unroll
            for (int off = 4; off > 0; off >>= 1)
                v += __shfl_down_sync(0xffu, v, off);
            if (tid == 0) out[(size_t)NROWS * Dv] = expf(-v);
        }
    }
}

// ---------------------------------------------------------------------------
extern "C" void kernel_launch(void* const* d_in, const int* in_sizes, int n_in,
                              void* d_out, int out_size) {
    const float* inputs = (const float*)d_in[0];   // (32, 64, 32, 32)
    const float* cb     = (const float*)d_in[1];   // (1024, 64)
    const float* noise  = (const float*)d_in[2];   // (32768, 64)
    float*       out    = (float*)d_out;

    cudaFuncSetAttribute(nsvq_hmma_kernel,
                         cudaFuncAttributeMaxDynamicSharedMemorySize, SMEM_DYN);

    nsvq_prep_kernel<<<(Kv * 8) / 256, 256>>>(cb);
    nsvq_hmma_kernel<<<GRID, THREADS, SMEM_DYN>>>(inputs, cb, noise, out);
}